// round 5
// baseline (speedup 1.0000x reference)
#include <cuda_runtime.h>
#include <math.h>
#include <stdint.h>

#define N_NODES 100000
#define N_EDGES 1000000
#define IN_DIM  128
#define HID     64
#define NET     4
#define G_GRAPHS 128
#define LBL     10
#define N_STEPS 5

// ---------------- scratch ----------------
static __device__ float g_h[(size_t)N_NODES * HID];
static __device__ float g_trans[(size_t)N_NODES * NET * HID];
static __device__ float g_a[(size_t)N_NODES * HID];
static __device__ int2  g_eoff[N_EDGES];
static __device__ uint32_t g_wih_hi[3 * HID * HID];
static __device__ uint32_t g_wih_lo[3 * HID * HID];
static __device__ uint32_t g_whh_hi[3 * HID * HID];
static __device__ uint32_t g_whh_lo[3 * HID * HID];
static __device__ float g_hg[G_GRAPHS * HID];
static __device__ float g_cnt[G_GRAPHS];

// ---------------- tf32 helpers ----------------
__device__ __forceinline__ uint32_t f2tf(float f) {
    uint32_t r; asm("cvt.rna.tf32.f32 %0, %1;" : "=r"(r) : "f"(f)); return r;
}
__device__ __forceinline__ void tfsplit(float x, uint32_t& hi, uint32_t& lo) {
    hi = f2tf(x);
    lo = f2tf(x - __uint_as_float(hi));
}
__device__ __forceinline__ void mma8(float* c, uint32_t a0, uint32_t a1, uint32_t a2, uint32_t a3,
                                     uint32_t b0, uint32_t b1) {
    asm volatile("mma.sync.aligned.m16n8k8.row.col.f32.tf32.tf32.f32 "
                 "{%0,%1,%2,%3},{%4,%5,%6,%7},{%8,%9},{%0,%1,%2,%3};"
                 : "+f"(c[0]), "+f"(c[1]), "+f"(c[2]), "+f"(c[3])
                 : "r"(a0), "r"(a1), "r"(a2), "r"(a3), "r"(b0), "r"(b1));
}

// ---------------- prep: edge offsets + split-tf32 GRU weights ----------------
__global__ void prep_kernel(const int* __restrict__ src, const int* __restrict__ dst,
                            const int* __restrict__ et,
                            const float* __restrict__ Wih, const float* __restrict__ Whh) {
    int t = blockIdx.x * blockDim.x + threadIdx.x;
    if (t < 3 * HID * HID) {
        tfsplit(__ldg(Wih + t), g_wih_hi[t], g_wih_lo[t]);
        tfsplit(__ldg(Whh + t), g_whh_hi[t], g_whh_lo[t]);
    }
    if (t < N_EDGES) {
        int s = __ldg(src + t), d = __ldg(dst + t), ty = __ldg(et + t);
        g_eoff[t] = make_int2((s * NET + ty) * HID, d * HID);
    }
}

// ---------------- split-tf32 GEMM: C[M,NCOLS] = A[M,K] @ W[NCOLS,K]^T + bias ----------------
// BM=128, BN=64 per block (grid.y covers NCOLS/64), 256 threads = 8 warps (4 row x 2 col).
// 3xTF32: C += Ahi*Bhi + Ahi*Blo + Alo*Bhi. Dynamic smem 96KB.
template<int K, int NCOLS>
__global__ void __launch_bounds__(256) tf32_gemm_split(
    const float* __restrict__ A, const float* __restrict__ W,
    const float* __restrict__ bias, float* __restrict__ C, int M)
{
    extern __shared__ uint32_t sm[];
    uint32_t* As_hi = sm;             // [8][32-lane][4]-frag order, 8192 u32
    uint32_t* As_lo = sm + 8192;
    uint32_t* Bs_hi = sm + 16384;     // [(half*2+wn)*8+ks][lane][4], 4096 u32
    uint32_t* Bs_lo = sm + 20480;

    const int tid  = threadIdx.x;
    const int row0 = blockIdx.x * 128;
    const int col0 = blockIdx.y * 64;
    const int warp = tid >> 5, lane = tid & 31;
    const int wm = warp & 3, wn = warp >> 2;

    float acc[2][4][4];
#pragma unroll
    for (int mt = 0; mt < 2; mt++)
#pragma unroll
        for (int nt = 0; nt < 4; nt++)
#pragma unroll
            for (int i = 0; i < 4; i++) acc[mt][nt][i] = 0.f;

    for (int kc = 0; kc < K; kc += 64) {
        // stage A tile 128x64 (hi/lo, fragment-permuted)
#pragma unroll
        for (int u = 0; u < 8; u++) {
            int c = tid + u * 256;
            int row = c >> 4, c0 = (c & 15) << 2;
            int gr = row0 + row; if (gr >= M) gr = M - 1;
            float4 v = __ldg((const float4*)(A + (size_t)gr * K + kc + c0));
            int reg  = (((row & 15) >= 8) ? 1 : 0) + (((c0 & 7) >= 4) ? 2 : 0);
            int base = (((row >> 4) * 8 + (c0 >> 3)) * 32 + (row & 7) * 4) * 4 + reg;
            uint32_t h0, l0;
            tfsplit(v.x, h0, l0); As_hi[base]      = h0; As_lo[base]      = l0;
            tfsplit(v.y, h0, l0); As_hi[base + 4]  = h0; As_lo[base + 4]  = l0;
            tfsplit(v.z, h0, l0); As_hi[base + 8]  = h0; As_lo[base + 8]  = l0;
            tfsplit(v.w, h0, l0); As_hi[base + 12] = h0; As_lo[base + 12] = l0;
        }
        // stage W tile 64x64 (hi/lo, lane-contiguous frag layout)
#pragma unroll
        for (int u = 0; u < 4; u++) {
            int c = tid + u * 256;
            int n = c >> 4, k0 = (c & 15) << 2;
            float4 v = __ldg((const float4*)(W + (size_t)(col0 + n) * K + kc + k0));
            int wnn  = n >> 5;
            int nt   = (n >> 3) & 3;
            int half = nt >> 1, ntl = nt & 1;
            int ks   = k0 >> 3;
            int reg  = ((k0 & 7) >= 4) ? 1 : 0;
            float vv[4] = {v.x, v.y, v.z, v.w};
#pragma unroll
            for (int j = 0; j < 4; j++) {
                int lp  = (n & 7) * 4 + j;   // lane position (tg = j)
                int idx = (((half * 2 + wnn) * 8 + ks) * 32 + lp) * 4 + ntl * 2 + reg;
                uint32_t hh, ll;
                tfsplit(vv[j], hh, ll);
                Bs_hi[idx] = hh; Bs_lo[idx] = ll;
            }
        }
        __syncthreads();
#pragma unroll
        for (int ks = 0; ks < 8; ks++) {
            uint4 ah[2], al[2];
#pragma unroll
            for (int mt = 0; mt < 2; mt++) {
                int ai = (((wm * 2 + mt) * 8 + ks) * 32 + lane) * 4;
                ah[mt] = *(const uint4*)&As_hi[ai];
                al[mt] = *(const uint4*)&As_lo[ai];
            }
            int b0i = (((0 * 2 + wn) * 8 + ks) * 32 + lane) * 4;
            int b1i = (((1 * 2 + wn) * 8 + ks) * 32 + lane) * 4;
            uint4 bh0 = *(const uint4*)&Bs_hi[b0i];
            uint4 bh1 = *(const uint4*)&Bs_hi[b1i];
            uint4 bl0 = *(const uint4*)&Bs_lo[b0i];
            uint4 bl1 = *(const uint4*)&Bs_lo[b1i];
            uint2 BH[4] = {{bh0.x, bh0.y}, {bh0.z, bh0.w}, {bh1.x, bh1.y}, {bh1.z, bh1.w}};
            uint2 BL[4] = {{bl0.x, bl0.y}, {bl0.z, bl0.w}, {bl1.x, bl1.y}, {bl1.z, bl1.w}};
#pragma unroll
            for (int mt = 0; mt < 2; mt++)
#pragma unroll
                for (int nt = 0; nt < 4; nt++) {
                    mma8(acc[mt][nt], ah[mt].x, ah[mt].y, ah[mt].z, ah[mt].w, BH[nt].x, BH[nt].y);
                    mma8(acc[mt][nt], ah[mt].x, ah[mt].y, ah[mt].z, ah[mt].w, BL[nt].x, BL[nt].y);
                    mma8(acc[mt][nt], al[mt].x, al[mt].y, al[mt].z, al[mt].w, BH[nt].x, BH[nt].y);
                }
        }
        __syncthreads();
    }

    const int g = lane >> 2, tg = lane & 3;
#pragma unroll
    for (int nt = 0; nt < 4; nt++) {
        int cc = col0 + wn * 32 + nt * 8 + tg * 2;
        float b0 = __ldg(bias + cc), b1 = __ldg(bias + cc + 1);
#pragma unroll
        for (int mt = 0; mt < 2; mt++) {
            int r = row0 + wm * 32 + mt * 16 + g;
            if (r < M)
                *(float2*)(C + (size_t)r * NCOLS + cc) =
                    make_float2(acc[mt][nt][0] + b0, acc[mt][nt][1] + b1);
            if (r + 8 < M)
                *(float2*)(C + (size_t)(r + 8) * NCOLS + cc) =
                    make_float2(acc[mt][nt][2] + b0, acc[mt][nt][3] + b1);
        }
    }
}

// ---------------- fused GRU (split tf32): gates + update + zero g_a ----------------
// BM=64 rows, 128 threads = 4 warps (2x2). Dynamic smem 64KB.
__global__ void __launch_bounds__(128) gru_fused_tf32(
    const float* __restrict__ bih, const float* __restrict__ bhh, int M)
{
    extern __shared__ uint32_t sm[];
    uint32_t* Aa_hi = sm;
    uint32_t* Aa_lo = sm + 4096;
    uint32_t* Ah_hi = sm + 8192;
    uint32_t* Ah_lo = sm + 12288;

    const int tid  = threadIdx.x;
    const int row0 = blockIdx.x * 64;
    const int warp = tid >> 5, lane = tid & 31;
    const int wm = warp & 1, wn = warp >> 1;
    const int g = lane >> 2, tg = lane & 3;

    // stage a and h tiles (hi/lo, fragment-permuted)
#pragma unroll
    for (int u = 0; u < 8; u++) {
        int c = tid + u * 128;
        int row = c >> 4, c0 = (c & 15) << 2;
        int gr = row0 + row; if (gr >= M) gr = M - 1;
        float4 va = __ldg((const float4*)(g_a + (size_t)gr * HID + c0));
        float4 vh = __ldg((const float4*)(g_h + (size_t)gr * HID + c0));
        int reg  = (((row & 15) >= 8) ? 1 : 0) + (((c0 & 7) >= 4) ? 2 : 0);
        int base = (((row >> 4) * 8 + (c0 >> 3)) * 32 + (row & 7) * 4) * 4 + reg;
        uint32_t hh, ll;
        tfsplit(va.x, hh, ll); Aa_hi[base]      = hh; Aa_lo[base]      = ll;
        tfsplit(va.y, hh, ll); Aa_hi[base + 4]  = hh; Aa_lo[base + 4]  = ll;
        tfsplit(va.z, hh, ll); Aa_hi[base + 8]  = hh; Aa_lo[base + 8]  = ll;
        tfsplit(va.w, hh, ll); Aa_hi[base + 12] = hh; Aa_lo[base + 12] = ll;
        tfsplit(vh.x, hh, ll); Ah_hi[base]      = hh; Ah_lo[base]      = ll;
        tfsplit(vh.y, hh, ll); Ah_hi[base + 4]  = hh; Ah_lo[base + 4]  = ll;
        tfsplit(vh.z, hh, ll); Ah_hi[base + 8]  = hh; Ah_lo[base + 8]  = ll;
        tfsplit(vh.w, hh, ll); Ah_hi[base + 12] = hh; Ah_lo[base + 12] = ll;
    }
    __syncthreads();

    float accR[2][4][4], accZ[2][4][4], accT[2][4][4];
#pragma unroll
    for (int mt = 0; mt < 2; mt++)
#pragma unroll
        for (int nt = 0; nt < 4; nt++)
#pragma unroll
            for (int i = 0; i < 4; i++) { accR[mt][nt][i] = 0.f; accZ[mt][nt][i] = 0.f; accT[mt][nt][i] = 0.f; }

    // helper macro: one K=64 pass (8 ks), splitting both operands.
#define GRU_PASS(ACC, AHI, ALO, WHI, WLO, SECOFF)                                             \
    {                                                                                          \
        const uint32_t* wbh = (WHI) + (size_t)((SECOFF) + wn * 32 + g) * HID + tg;             \
        const uint32_t* wbl = (WLO) + (size_t)((SECOFF) + wn * 32 + g) * HID + tg;             \
        _Pragma("unroll")                                                                      \
        for (int ks = 0; ks < 8; ks++) {                                                       \
            uint4 avh[2], avl[2];                                                              \
            _Pragma("unroll")                                                                  \
            for (int mt = 0; mt < 2; mt++) {                                                   \
                int ai = (((wm * 2 + mt) * 8 + ks) * 32 + lane) * 4;                           \
                avh[mt] = *(const uint4*)&(AHI)[ai];                                           \
                avl[mt] = *(const uint4*)&(ALO)[ai];                                           \
            }                                                                                  \
            _Pragma("unroll")                                                                  \
            for (int nt = 0; nt < 4; nt++) {                                                   \
                uint32_t b0 = __ldg(wbh + nt * 8 * HID + ks * 8);                              \
                uint32_t b1 = __ldg(wbh + nt * 8 * HID + ks * 8 + 4);                          \
                uint32_t l0 = __ldg(wbl + nt * 8 * HID + ks * 8);                              \
                uint32_t l1 = __ldg(wbl + nt * 8 * HID + ks * 8 + 4);                          \
                _Pragma("unroll")                                                              \
                for (int mt = 0; mt < 2; mt++) {                                               \
                    mma8(ACC[mt][nt], avh[mt].x, avh[mt].y, avh[mt].z, avh[mt].w, b0, b1);     \
                    mma8(ACC[mt][nt], avh[mt].x, avh[mt].y, avh[mt].z, avh[mt].w, l0, l1);     \
                    mma8(ACC[mt][nt], avl[mt].x, avl[mt].y, avl[mt].z, avl[mt].w, b0, b1);     \
                }                                                                              \
            }                                                                                  \
        }                                                                                      \
    }

    // R and Z sections: both passes (a@Wih, h@Whh)
    GRU_PASS(accR, Aa_hi, Aa_lo, g_wih_hi, g_wih_lo, 0)
    GRU_PASS(accR, Ah_hi, Ah_lo, g_whh_hi, g_whh_lo, 0)
    GRU_PASS(accZ, Aa_hi, Aa_lo, g_wih_hi, g_wih_lo, 64)
    GRU_PASS(accZ, Ah_hi, Ah_lo, g_whh_hi, g_whh_lo, 64)
    // accT = h @ Whh_n
    GRU_PASS(accT, Ah_hi, Ah_lo, g_whh_hi, g_whh_lo, 128)

    // r = sigmoid(accR + br); accT = r * (accT + bhn)
#pragma unroll
    for (int nt = 0; nt < 4; nt++) {
        int cc = wn * 32 + nt * 8 + tg * 2;
        float br0 = __ldg(bih + cc) + __ldg(bhh + cc);
        float br1 = __ldg(bih + cc + 1) + __ldg(bhh + cc + 1);
        float bn0 = __ldg(bhh + 128 + cc);
        float bn1 = __ldg(bhh + 128 + cc + 1);
#pragma unroll
        for (int mt = 0; mt < 2; mt++)
#pragma unroll
            for (int i = 0; i < 4; i++) {
                float brv = (i & 1) ? br1 : br0;
                float bnv = (i & 1) ? bn1 : bn0;
                float r = 1.f / (1.f + __expf(-(accR[mt][nt][i] + brv)));
                accT[mt][nt][i] = r * (accT[mt][nt][i] + bnv);
            }
    }

    // accT += a @ Wih_n
    GRU_PASS(accT, Aa_hi, Aa_lo, g_wih_hi, g_wih_lo, 128)
#undef GRU_PASS

    // epilogue: z, n, h update; zero g_a for next step's scatter
#pragma unroll
    for (int nt = 0; nt < 4; nt++) {
        int cc = wn * 32 + nt * 8 + tg * 2;
        float bz0 = __ldg(bih + 64 + cc) + __ldg(bhh + 64 + cc);
        float bz1 = __ldg(bih + 64 + cc + 1) + __ldg(bhh + 64 + cc + 1);
        float bi0 = __ldg(bih + 128 + cc);
        float bi1 = __ldg(bih + 128 + cc + 1);
#pragma unroll
        for (int mt = 0; mt < 2; mt++) {
#pragma unroll
            for (int half = 0; half < 2; half++) {
                int r = row0 + wm * 32 + mt * 16 + g + half * 8;
                if (r < M) {
                    float* hp = g_h + (size_t)r * HID + cc;
                    float2 ho = *(const float2*)hp;
                    int i0 = half * 2;
                    float z0 = 1.f / (1.f + __expf(-(accZ[mt][nt][i0] + bz0)));
                    float z1 = 1.f / (1.f + __expf(-(accZ[mt][nt][i0 + 1] + bz1)));
                    float n0 = tanhf(accT[mt][nt][i0] + bi0);
                    float n1 = tanhf(accT[mt][nt][i0 + 1] + bi1);
                    *(float2*)hp = make_float2((1.f - z0) * n0 + z0 * ho.x,
                                               (1.f - z1) * n1 + z1 * ho.y);
                    *(float2*)(g_a + (size_t)r * HID + cc) = make_float2(0.f, 0.f);
                }
            }
        }
    }
}

// ---------------- zero helpers ----------------
__global__ void zero_a() {
    size_t t = (size_t)blockIdx.x * blockDim.x + threadIdx.x;
    size_t n4 = (size_t)N_NODES * HID / 4;
    if (t < n4) ((float4*)g_a)[t] = make_float4(0.f, 0.f, 0.f, 0.f);
}
__global__ void zero_pool() {
    int t = threadIdx.x;
    for (int i = t; i < G_GRAPHS * HID; i += blockDim.x) g_hg[i] = 0.f;
    if (t < G_GRAPHS) g_cnt[t] = 0.f;
}

// ---------------- edge scatter: 4 edges per 16-thread group, MLP=4 ----------------
__global__ void edge_scatter4() {
    int t = blockIdx.x * blockDim.x + threadIdx.x;
    int grp = t >> 4;                      // each group: 4 consecutive edges
    if (grp >= N_EDGES / 4) return;
    int q = (t & 15) << 2;
    const int4* eo = (const int4*)g_eoff;
    int4 p01 = __ldg(eo + grp * 2);        // (src0,dst0,src1,dst1)
    int4 p23 = __ldg(eo + grp * 2 + 1);    // (src2,dst2,src3,dst3)
    float4 v0 = __ldg((const float4*)&g_trans[(size_t)p01.x + q]);
    float4 v1 = __ldg((const float4*)&g_trans[(size_t)p01.z + q]);
    float4 v2 = __ldg((const float4*)&g_trans[(size_t)p23.x + q]);
    float4 v3 = __ldg((const float4*)&g_trans[(size_t)p23.z + q]);
    asm volatile("red.global.add.v4.f32 [%0], {%1,%2,%3,%4};"
                 :: "l"(&g_a[(size_t)p01.y + q]), "f"(v0.x), "f"(v0.y), "f"(v0.z), "f"(v0.w) : "memory");
    asm volatile("red.global.add.v4.f32 [%0], {%1,%2,%3,%4};"
                 :: "l"(&g_a[(size_t)p01.w + q]), "f"(v1.x), "f"(v1.y), "f"(v1.z), "f"(v1.w) : "memory");
    asm volatile("red.global.add.v4.f32 [%0], {%1,%2,%3,%4};"
                 :: "l"(&g_a[(size_t)p23.y + q]), "f"(v2.x), "f"(v2.y), "f"(v2.z), "f"(v2.w) : "memory");
    asm volatile("red.global.add.v4.f32 [%0], {%1,%2,%3,%4};"
                 :: "l"(&g_a[(size_t)p23.w + q]), "f"(v3.x), "f"(v3.y), "f"(v3.z), "f"(v3.w) : "memory");
}

// ---------------- per-graph mean pool ----------------
__global__ void pool_kernel(const int* __restrict__ n2g) {
    constexpr int CHUNK = 256;
    int j = threadIdx.x;
    int start = blockIdx.x * CHUNK;
    int end   = min(start + CHUNK, N_NODES);
    if (start >= end) return;
    float sum = 0.f, c = 0.f;
    int g = __ldg(n2g + start);
    for (int n = start; n < end; n++) {
        int gn = __ldg(n2g + n);
        if (gn != g) {
            atomicAdd(&g_hg[g * HID + j], sum);
            if (j == 0) atomicAdd(&g_cnt[g], c);
            sum = 0.f; c = 0.f; g = gn;
        }
        sum += g_h[(size_t)n * HID + j];
        c += 1.f;
    }
    atomicAdd(&g_hg[g * HID + j], sum);
    if (j == 0) atomicAdd(&g_cnt[g], c);
}

// ---------------- classifier ----------------
__global__ void classifier_kernel(const float* __restrict__ W1, const float* __restrict__ b1,
                                  const float* __restrict__ W2, const float* __restrict__ b2,
                                  float* __restrict__ out)
{
    __shared__ float sW1[32 * 64];
    __shared__ float sW2[10 * 32];
    __shared__ float sHG[G_GRAPHS][HID + 1];
    int t = threadIdx.x;
    for (int i = t; i < 32 * 64; i += 128) sW1[i] = W1[i];
    for (int i = t; i < 10 * 32; i += 128) sW2[i] = W2[i];
    for (int i = t; i < G_GRAPHS * HID; i += 128) {
        int g = i >> 6;
        sHG[g][i & 63] = g_hg[i] / fmaxf(g_cnt[g], 1.f);
    }
    __syncthreads();
    int g = t;
    float mid[32];
#pragma unroll
    for (int m = 0; m < 32; m++) {
        float s = b1[m];
#pragma unroll
        for (int k = 0; k < 64; k++) s += sHG[g][k] * sW1[m * 64 + k];
        mid[m] = fmaxf(s, 0.f);
    }
#pragma unroll
    for (int l = 0; l < LBL; l++) {
        float s = b2[l];
#pragma unroll
        for (int k = 0; k < 32; k++) s += mid[k] * sW2[l * 32 + k];
        out[g * LBL + l] = s;
    }
}

// ---------------- launch ----------------
extern "C" void kernel_launch(void* const* d_in, const int* in_sizes, int n_in,
                              void* d_out, int out_size)
{
    const float* x    = (const float*)d_in[0];
    const int*   src  = (const int*)d_in[1];
    const int*   dst  = (const int*)d_in[2];
    const int*   et   = (const int*)d_in[3];
    const int*   n2g  = (const int*)d_in[4];
    const float* W_in = (const float*)d_in[5];
    const float* b_in = (const float*)d_in[6];
    const float* We   = (const float*)d_in[7];
    const float* be   = (const float*)d_in[8];
    const float* W_ih = (const float*)d_in[9];
    const float* b_ih = (const float*)d_in[10];
    const float* W_hh = (const float*)d_in[11];
    const float* b_hh = (const float*)d_in[12];
    const float* W1   = (const float*)d_in[13];
    const float* b1   = (const float*)d_in[14];
    const float* W2   = (const float*)d_in[15];
    const float* b2   = (const float*)d_in[16];
    float* out = (float*)d_out;

    void *p;
    cudaGetSymbolAddress(&p, g_h);     float* ph  = (float*)p;
    cudaGetSymbolAddress(&p, g_trans); float* ptr = (float*)p;

    const size_t GEMM_SMEM = 96 * 1024;
    const size_t GRU_SMEM  = 64 * 1024;
    cudaFuncSetAttribute(tf32_gemm_split<IN_DIM, HID>,
                         cudaFuncAttributeMaxDynamicSharedMemorySize, (int)GEMM_SMEM);
    cudaFuncSetAttribute(tf32_gemm_split<HID, NET * HID>,
                         cudaFuncAttributeMaxDynamicSharedMemorySize, (int)GEMM_SMEM);
    cudaFuncSetAttribute(gru_fused_tf32,
                         cudaFuncAttributeMaxDynamicSharedMemorySize, (int)GRU_SMEM);

    const int M = N_NODES;
    const int gx = (M + 127) / 128;

    prep_kernel<<<(N_EDGES + 255) / 256, 256>>>(src, dst, et, W_ih, W_hh);
    zero_a<<<((N_NODES * HID / 4) + 255) / 256, 256>>>();

    // h = x @ W_in^T + b_in
    tf32_gemm_split<IN_DIM, HID><<<dim3(gx, 1), 256, GEMM_SMEM>>>(x, W_in, b_in, ph, M);

    for (int s = 0; s < N_STEPS; s++) {
        tf32_gemm_split<HID, NET * HID><<<dim3(gx, NET), 256, GEMM_SMEM>>>(ph, We, be, ptr, M);
        edge_scatter4<<<(N_EDGES / 4 * 16 + 255) / 256, 256>>>();
        gru_fused_tf32<<<(M + 63) / 64, 128, GRU_SMEM>>>(b_ih, b_hh, M);  // also zeroes g_a
    }

    zero_pool<<<1, 256>>>();
    pool_kernel<<<(M + 255) / 256, 64>>>(n2g);
    classifier_kernel<<<1, 128>>>(W1, b1, W2, b2, out);
}

// round 6
// speedup vs baseline: 1.2753x; 1.2753x over previous
#include <cuda_runtime.h>
#include <math.h>
#include <stdint.h>

#define N_NODES 100000
#define N_EDGES 1000000
#define IN_DIM  128
#define HID     64
#define NET     4
#define G_GRAPHS 128
#define LBL     10
#define N_STEPS 5

// ---------------- scratch ----------------
static __device__ float g_h[(size_t)N_NODES * HID];
static __device__ float g_trans[(size_t)N_NODES * NET * HID];
static __device__ float g_a[(size_t)N_NODES * HID];
static __device__ int2  g_eoff[N_EDGES];
// fragment-packed tf32 weights: uint4 = (b0hi, b1hi, b0lo, b1lo)
// index: (row * (K/8) + kb) * 4 + tg ; b0 = W[row][kb*8+tg], b1 = W[row][kb*8+tg+4]
static __device__ uint4 g_winf[HID * (IN_DIM / 8) * 4];          // 64x16x4
static __device__ uint4 g_wef [NET * HID * (HID / 8) * 4];       // 256x8x4
static __device__ uint4 g_wihf[3 * HID * (HID / 8) * 4];         // 192x8x4
static __device__ uint4 g_whhf[3 * HID * (HID / 8) * 4];
static __device__ float g_hg[G_GRAPHS * HID];
static __device__ float g_cnt[G_GRAPHS];

// ---------------- tf32 helpers ----------------
__device__ __forceinline__ uint32_t f2tf(float f) {
    uint32_t r; asm("cvt.rna.tf32.f32 %0, %1;" : "=r"(r) : "f"(f)); return r;
}
__device__ __forceinline__ void tfsplit(float x, uint32_t& hi, uint32_t& lo) {
    hi = f2tf(x);
    lo = f2tf(x - __uint_as_float(hi));
}
__device__ __forceinline__ void mma8(float* c, uint32_t a0, uint32_t a1, uint32_t a2, uint32_t a3,
                                     uint32_t b0, uint32_t b1) {
    asm volatile("mma.sync.aligned.m16n8k8.row.col.f32.tf32.tf32.f32 "
                 "{%0,%1,%2,%3},{%4,%5,%6,%7},{%8,%9},{%0,%1,%2,%3};"
                 : "+f"(c[0]), "+f"(c[1]), "+f"(c[2]), "+f"(c[3])
                 : "r"(a0), "r"(a1), "r"(a2), "r"(a3), "r"(b0), "r"(b1));
}

// ---------------- prep: edge offsets + fragment-packed split weights ----------------
__device__ __forceinline__ void pack_frag(uint4* F, const float* __restrict__ W, int K, int t) {
    int tg  = t & 3;
    int kb  = (t >> 2) % (K / 8);
    int row = (t >> 2) / (K / 8);
    float x0 = __ldg(W + row * K + kb * 8 + tg);
    float x1 = __ldg(W + row * K + kb * 8 + tg + 4);
    uint4 f;
    tfsplit(x0, f.x, f.z);
    tfsplit(x1, f.y, f.w);
    F[t] = f;
}

__global__ void prep_kernel(const int* __restrict__ src, const int* __restrict__ dst,
                            const int* __restrict__ et,
                            const float* __restrict__ Win, const float* __restrict__ We,
                            const float* __restrict__ Wih, const float* __restrict__ Whh) {
    int t = blockIdx.x * blockDim.x + threadIdx.x;
    if (t < HID * (IN_DIM / 8) * 4)      pack_frag(g_winf, Win, IN_DIM, t);
    if (t < NET * HID * (HID / 8) * 4)   pack_frag(g_wef,  We,  HID, t);
    if (t < 3 * HID * (HID / 8) * 4) {
        pack_frag(g_wihf, Wih, HID, t);
        pack_frag(g_whhf, Whh, HID, t);
    }
    if (t < N_EDGES) {
        int s = __ldg(src + t), d = __ldg(dst + t), ty = __ldg(et + t);
        g_eoff[t] = make_int2((s * NET + ty) * HID, d * HID);
    }
}

// ---------------- split-tf32 GEMM, B from packed global frags ----------------
// BM=128, BN=64 per block (grid.y covers NCOLS/64), 256 threads = 8 warps (4m x 2n).
// smem: A hi/lo only (64KB). 3xTF32: C += Ahi*Bhi + Ahi*Blo + Alo*Bhi.
template<int K, int NCOLS>
__global__ void __launch_bounds__(256) tf32_gemm_frag(
    const float* __restrict__ A, const uint4* __restrict__ WF,
    const float* __restrict__ bias, float* __restrict__ C, int M)
{
    extern __shared__ uint32_t sm[];
    uint32_t* As_hi = sm;            // 8192 u32
    uint32_t* As_lo = sm + 8192;     // 8192 u32

    const int tid  = threadIdx.x;
    const int row0 = blockIdx.x * 128;
    const int col0 = blockIdx.y * 64;
    const int warp = tid >> 5, lane = tid & 31;
    const int wm = warp & 3, wn = warp >> 2;
    const int g = lane >> 2, tg = lane & 3;

    float acc[2][4][4];
#pragma unroll
    for (int mt = 0; mt < 2; mt++)
#pragma unroll
        for (int nt = 0; nt < 4; nt++)
#pragma unroll
            for (int i = 0; i < 4; i++) acc[mt][nt][i] = 0.f;

    // per-nt packed-fragment base pointers (row = col0 + wn*32 + nt*8 + g)
    const uint4* wb[4];
#pragma unroll
    for (int nt = 0; nt < 4; nt++)
        wb[nt] = WF + (size_t)(col0 + wn * 32 + nt * 8 + g) * (K / 8) * 4 + tg;

    for (int kc = 0; kc < K; kc += 64) {
        // stage A tile 128x64 hi/lo, fragment-permuted
#pragma unroll
        for (int u = 0; u < 8; u++) {
            int c = tid + u * 256;
            int row = c >> 4, c0 = (c & 15) << 2;
            int gr = row0 + row; if (gr >= M) gr = M - 1;
            float4 v = __ldg((const float4*)(A + (size_t)gr * K + kc + c0));
            int reg  = (((row & 15) >= 8) ? 1 : 0) + (((c0 & 7) >= 4) ? 2 : 0);
            int base = (((row >> 4) * 8 + (c0 >> 3)) * 32 + (row & 7) * 4) * 4 + reg;
            uint32_t hh, ll;
            tfsplit(v.x, hh, ll); As_hi[base]      = hh; As_lo[base]      = ll;
            tfsplit(v.y, hh, ll); As_hi[base + 4]  = hh; As_lo[base + 4]  = ll;
            tfsplit(v.z, hh, ll); As_hi[base + 8]  = hh; As_lo[base + 8]  = ll;
            tfsplit(v.w, hh, ll); As_hi[base + 12] = hh; As_lo[base + 12] = ll;
        }
        __syncthreads();
        const int kb0 = kc >> 3;
#pragma unroll
        for (int ks = 0; ks < 8; ks++) {
            uint4 ah[2], al[2];
#pragma unroll
            for (int mt = 0; mt < 2; mt++) {
                int ai = (((wm * 2 + mt) * 8 + ks) * 32 + lane) * 4;
                ah[mt] = *(const uint4*)&As_hi[ai];
                al[mt] = *(const uint4*)&As_lo[ai];
            }
            uint4 bf[4];
#pragma unroll
            for (int nt = 0; nt < 4; nt++)
                bf[nt] = __ldg(wb[nt] + (kb0 + ks) * 4);
#pragma unroll
            for (int mt = 0; mt < 2; mt++)
#pragma unroll
                for (int nt = 0; nt < 4; nt++) {
                    mma8(acc[mt][nt], ah[mt].x, ah[mt].y, ah[mt].z, ah[mt].w, bf[nt].x, bf[nt].y);
                    mma8(acc[mt][nt], ah[mt].x, ah[mt].y, ah[mt].z, ah[mt].w, bf[nt].z, bf[nt].w);
                    mma8(acc[mt][nt], al[mt].x, al[mt].y, al[mt].z, al[mt].w, bf[nt].x, bf[nt].y);
                }
        }
        __syncthreads();
    }

    // epilogue
#pragma unroll
    for (int nt = 0; nt < 4; nt++) {
        int cc = col0 + wn * 32 + nt * 8 + tg * 2;
        float b0 = __ldg(bias + cc), b1 = __ldg(bias + cc + 1);
#pragma unroll
        for (int mt = 0; mt < 2; mt++) {
            int r = row0 + wm * 32 + mt * 16 + g;
            if (r < M)
                *(float2*)(C + (size_t)r * NCOLS + cc) =
                    make_float2(acc[mt][nt][0] + b0, acc[mt][nt][1] + b1);
            if (r + 8 < M)
                *(float2*)(C + (size_t)(r + 8) * NCOLS + cc) =
                    make_float2(acc[mt][nt][2] + b0, acc[mt][nt][3] + b1);
        }
    }
}

// ---------------- fused GRU (split tf32, packed W frags): gates + update + zero g_a ----------------
// BM=64 rows, 128 threads = 4 warps (2m x 2n), smem 64KB.
__global__ void __launch_bounds__(128) gru_fused_tf32(
    const float* __restrict__ bih, const float* __restrict__ bhh, int M)
{
    extern __shared__ uint32_t sm[];
    uint32_t* Aa_hi = sm;
    uint32_t* Aa_lo = sm + 4096;
    uint32_t* Ah_hi = sm + 8192;
    uint32_t* Ah_lo = sm + 12288;

    const int tid  = threadIdx.x;
    const int row0 = blockIdx.x * 64;
    const int warp = tid >> 5, lane = tid & 31;
    const int wm = warp & 1, wn = warp >> 1;
    const int g = lane >> 2, tg = lane & 3;

    // stage a and h tiles (hi/lo, fragment-permuted)
#pragma unroll
    for (int u = 0; u < 8; u++) {
        int c = tid + u * 128;
        int row = c >> 4, c0 = (c & 15) << 2;
        int gr = row0 + row; if (gr >= M) gr = M - 1;
        float4 va = __ldg((const float4*)(g_a + (size_t)gr * HID + c0));
        float4 vh = __ldg((const float4*)(g_h + (size_t)gr * HID + c0));
        int reg  = (((row & 15) >= 8) ? 1 : 0) + (((c0 & 7) >= 4) ? 2 : 0);
        int base = (((row >> 4) * 8 + (c0 >> 3)) * 32 + (row & 7) * 4) * 4 + reg;
        uint32_t hh, ll;
        tfsplit(va.x, hh, ll); Aa_hi[base]      = hh; Aa_lo[base]      = ll;
        tfsplit(va.y, hh, ll); Aa_hi[base + 4]  = hh; Aa_lo[base + 4]  = ll;
        tfsplit(va.z, hh, ll); Aa_hi[base + 8]  = hh; Aa_lo[base + 8]  = ll;
        tfsplit(va.w, hh, ll); Aa_hi[base + 12] = hh; Aa_lo[base + 12] = ll;
        tfsplit(vh.x, hh, ll); Ah_hi[base]      = hh; Ah_lo[base]      = ll;
        tfsplit(vh.y, hh, ll); Ah_hi[base + 4]  = hh; Ah_lo[base + 4]  = ll;
        tfsplit(vh.z, hh, ll); Ah_hi[base + 8]  = hh; Ah_lo[base + 8]  = ll;
        tfsplit(vh.w, hh, ll); Ah_hi[base + 12] = hh; Ah_lo[base + 12] = ll;
    }
    __syncthreads();

    float accR[2][4][4], accZ[2][4][4], accT[2][4][4];
#pragma unroll
    for (int mt = 0; mt < 2; mt++)
#pragma unroll
        for (int nt = 0; nt < 4; nt++)
#pragma unroll
            for (int i = 0; i < 4; i++) { accR[mt][nt][i] = 0.f; accZ[mt][nt][i] = 0.f; accT[mt][nt][i] = 0.f; }

    // one K=64 pass over a section of packed weights (SECOFF in rows)
#define GRU_PASS(ACC, AHI, ALO, WF, SECOFF)                                                   \
    {                                                                                          \
        const uint4* wbp[4];                                                                   \
        _Pragma("unroll")                                                                      \
        for (int nt = 0; nt < 4; nt++)                                                         \
            wbp[nt] = (WF) + (size_t)((SECOFF) + wn * 32 + nt * 8 + g) * 8 * 4 + tg;           \
        _Pragma("unroll")                                                                      \
        for (int ks = 0; ks < 8; ks++) {                                                       \
            uint4 avh[2], avl[2];                                                              \
            _Pragma("unroll")                                                                  \
            for (int mt = 0; mt < 2; mt++) {                                                   \
                int ai = (((wm * 2 + mt) * 8 + ks) * 32 + lane) * 4;                           \
                avh[mt] = *(const uint4*)&(AHI)[ai];                                           \
                avl[mt] = *(const uint4*)&(ALO)[ai];                                           \
            }                                                                                  \
            _Pragma("unroll")                                                                  \
            for (int nt = 0; nt < 4; nt++) {                                                   \
                uint4 bf = __ldg(wbp[nt] + ks * 4);                                            \
                _Pragma("unroll")                                                              \
                for (int mt = 0; mt < 2; mt++) {                                               \
                    mma8(ACC[mt][nt], avh[mt].x, avh[mt].y, avh[mt].z, avh[mt].w, bf.x, bf.y); \
                    mma8(ACC[mt][nt], avh[mt].x, avh[mt].y, avh[mt].z, avh[mt].w, bf.z, bf.w); \
                    mma8(ACC[mt][nt], avl[mt].x, avl[mt].y, avl[mt].z, avl[mt].w, bf.x, bf.y); \
                }                                                                              \
            }                                                                                  \
        }                                                                                      \
    }

    GRU_PASS(accR, Aa_hi, Aa_lo, g_wihf, 0)
    GRU_PASS(accR, Ah_hi, Ah_lo, g_whhf, 0)
    GRU_PASS(accZ, Aa_hi, Aa_lo, g_wihf, 64)
    GRU_PASS(accZ, Ah_hi, Ah_lo, g_whhf, 64)
    GRU_PASS(accT, Ah_hi, Ah_lo, g_whhf, 128)

    // r = sigmoid(accR + br); accT = r * (accT + bhn)
#pragma unroll
    for (int nt = 0; nt < 4; nt++) {
        int cc = wn * 32 + nt * 8 + tg * 2;
        float br0 = __ldg(bih + cc) + __ldg(bhh + cc);
        float br1 = __ldg(bih + cc + 1) + __ldg(bhh + cc + 1);
        float bn0 = __ldg(bhh + 128 + cc);
        float bn1 = __ldg(bhh + 128 + cc + 1);
#pragma unroll
        for (int mt = 0; mt < 2; mt++)
#pragma unroll
            for (int i = 0; i < 4; i++) {
                float brv = (i & 1) ? br1 : br0;
                float bnv = (i & 1) ? bn1 : bn0;
                float r = 1.f / (1.f + __expf(-(accR[mt][nt][i] + brv)));
                accT[mt][nt][i] = r * (accT[mt][nt][i] + bnv);
            }
    }

    GRU_PASS(accT, Aa_hi, Aa_lo, g_wihf, 128)
#undef GRU_PASS

    // epilogue: z, n, h update; zero g_a for next step's scatter
#pragma unroll
    for (int nt = 0; nt < 4; nt++) {
        int cc = wn * 32 + nt * 8 + tg * 2;
        float bz0 = __ldg(bih + 64 + cc) + __ldg(bhh + 64 + cc);
        float bz1 = __ldg(bih + 64 + cc + 1) + __ldg(bhh + 64 + cc + 1);
        float bi0 = __ldg(bih + 128 + cc);
        float bi1 = __ldg(bih + 128 + cc + 1);
#pragma unroll
        for (int mt = 0; mt < 2; mt++) {
#pragma unroll
            for (int half = 0; half < 2; half++) {
                int r = row0 + wm * 32 + mt * 16 + g + half * 8;
                if (r < M) {
                    float* hp = g_h + (size_t)r * HID + cc;
                    float2 ho = *(const float2*)hp;
                    int i0 = half * 2;
                    float z0 = 1.f / (1.f + __expf(-(accZ[mt][nt][i0] + bz0)));
                    float z1 = 1.f / (1.f + __expf(-(accZ[mt][nt][i0 + 1] + bz1)));
                    float n0 = tanhf(accT[mt][nt][i0] + bi0);
                    float n1 = tanhf(accT[mt][nt][i0 + 1] + bi1);
                    *(float2*)hp = make_float2((1.f - z0) * n0 + z0 * ho.x,
                                               (1.f - z1) * n1 + z1 * ho.y);
                    *(float2*)(g_a + (size_t)r * HID + cc) = make_float2(0.f, 0.f);
                }
            }
        }
    }
}

// ---------------- zero helpers ----------------
__global__ void zero_a() {
    size_t t = (size_t)blockIdx.x * blockDim.x + threadIdx.x;
    size_t n4 = (size_t)N_NODES * HID / 4;
    if (t < n4) ((float4*)g_a)[t] = make_float4(0.f, 0.f, 0.f, 0.f);
}
__global__ void zero_pool() {
    int t = threadIdx.x;
    for (int i = t; i < G_GRAPHS * HID; i += blockDim.x) g_hg[i] = 0.f;
    if (t < G_GRAPHS) g_cnt[t] = 0.f;
}

// ---------------- edge scatter: 4 edges per 16-thread group, MLP=4 ----------------
__global__ void edge_scatter4() {
    int t = blockIdx.x * blockDim.x + threadIdx.x;
    int grp = t >> 4;
    if (grp >= N_EDGES / 4) return;
    int q = (t & 15) << 2;
    const int4* eo = (const int4*)g_eoff;
    int4 p01 = __ldg(eo + grp * 2);
    int4 p23 = __ldg(eo + grp * 2 + 1);
    float4 v0 = __ldg((const float4*)&g_trans[(size_t)p01.x + q]);
    float4 v1 = __ldg((const float4*)&g_trans[(size_t)p01.z + q]);
    float4 v2 = __ldg((const float4*)&g_trans[(size_t)p23.x + q]);
    float4 v3 = __ldg((const float4*)&g_trans[(size_t)p23.z + q]);
    asm volatile("red.global.add.v4.f32 [%0], {%1,%2,%3,%4};"
                 :: "l"(&g_a[(size_t)p01.y + q]), "f"(v0.x), "f"(v0.y), "f"(v0.z), "f"(v0.w) : "memory");
    asm volatile("red.global.add.v4.f32 [%0], {%1,%2,%3,%4};"
                 :: "l"(&g_a[(size_t)p01.w + q]), "f"(v1.x), "f"(v1.y), "f"(v1.z), "f"(v1.w) : "memory");
    asm volatile("red.global.add.v4.f32 [%0], {%1,%2,%3,%4};"
                 :: "l"(&g_a[(size_t)p23.y + q]), "f"(v2.x), "f"(v2.y), "f"(v2.z), "f"(v2.w) : "memory");
    asm volatile("red.global.add.v4.f32 [%0], {%1,%2,%3,%4};"
                 :: "l"(&g_a[(size_t)p23.w + q]), "f"(v3.x), "f"(v3.y), "f"(v3.z), "f"(v3.w) : "memory");
}

// ---------------- per-graph mean pool ----------------
__global__ void pool_kernel(const int* __restrict__ n2g) {
    constexpr int CHUNK = 256;
    int j = threadIdx.x;
    int start = blockIdx.x * CHUNK;
    int end   = min(start + CHUNK, N_NODES);
    if (start >= end) return;
    float sum = 0.f, c = 0.f;
    int g = __ldg(n2g + start);
    for (int n = start; n < end; n++) {
        int gn = __ldg(n2g + n);
        if (gn != g) {
            atomicAdd(&g_hg[g * HID + j], sum);
            if (j == 0) atomicAdd(&g_cnt[g], c);
            sum = 0.f; c = 0.f; g = gn;
        }
        sum += g_h[(size_t)n * HID + j];
        c += 1.f;
    }
    atomicAdd(&g_hg[g * HID + j], sum);
    if (j == 0) atomicAdd(&g_cnt[g], c);
}

// ---------------- classifier ----------------
__global__ void classifier_kernel(const float* __restrict__ W1, const float* __restrict__ b1,
                                  const float* __restrict__ W2, const float* __restrict__ b2,
                                  float* __restrict__ out)
{
    __shared__ float sW1[32 * 64];
    __shared__ float sW2[10 * 32];
    __shared__ float sHG[G_GRAPHS][HID + 1];
    int t = threadIdx.x;
    for (int i = t; i < 32 * 64; i += 128) sW1[i] = W1[i];
    for (int i = t; i < 10 * 32; i += 128) sW2[i] = W2[i];
    for (int i = t; i < G_GRAPHS * HID; i += 128) {
        int g = i >> 6;
        sHG[g][i & 63] = g_hg[i] / fmaxf(g_cnt[g], 1.f);
    }
    __syncthreads();
    int g = t;
    float mid[32];
#pragma unroll
    for (int m = 0; m < 32; m++) {
        float s = b1[m];
#pragma unroll
        for (int k = 0; k < 64; k++) s += sHG[g][k] * sW1[m * 64 + k];
        mid[m] = fmaxf(s, 0.f);
    }
#pragma unroll
    for (int l = 0; l < LBL; l++) {
        float s = b2[l];
#pragma unroll
        for (int k = 0; k < 32; k++) s += mid[k] * sW2[l * 32 + k];
        out[g * LBL + l] = s;
    }
}

// ---------------- launch ----------------
extern "C" void kernel_launch(void* const* d_in, const int* in_sizes, int n_in,
                              void* d_out, int out_size)
{
    const float* x    = (const float*)d_in[0];
    const int*   src  = (const int*)d_in[1];
    const int*   dst  = (const int*)d_in[2];
    const int*   et   = (const int*)d_in[3];
    const int*   n2g  = (const int*)d_in[4];
    const float* W_in = (const float*)d_in[5];
    const float* b_in = (const float*)d_in[6];
    const float* We   = (const float*)d_in[7];
    const float* be   = (const float*)d_in[8];
    const float* W_ih = (const float*)d_in[9];
    const float* b_ih = (const float*)d_in[10];
    const float* W_hh = (const float*)d_in[11];
    const float* b_hh = (const float*)d_in[12];
    const float* W1   = (const float*)d_in[13];
    const float* b1   = (const float*)d_in[14];
    const float* W2   = (const float*)d_in[15];
    const float* b2   = (const float*)d_in[16];
    float* out = (float*)d_out;

    void *p;
    cudaGetSymbolAddress(&p, g_h);     float* ph  = (float*)p;
    cudaGetSymbolAddress(&p, g_trans); float* ptr = (float*)p;
    cudaGetSymbolAddress(&p, g_winf);  const uint4* pwin = (const uint4*)p;
    cudaGetSymbolAddress(&p, g_wef);   const uint4* pwe  = (const uint4*)p;

    const size_t GEMM_SMEM = 64 * 1024;
    const size_t GRU_SMEM  = 64 * 1024;
    cudaFuncSetAttribute(tf32_gemm_frag<IN_DIM, HID>,
                         cudaFuncAttributeMaxDynamicSharedMemorySize, (int)GEMM_SMEM);
    cudaFuncSetAttribute(tf32_gemm_frag<HID, NET * HID>,
                         cudaFuncAttributeMaxDynamicSharedMemorySize, (int)GEMM_SMEM);
    cudaFuncSetAttribute(gru_fused_tf32,
                         cudaFuncAttributeMaxDynamicSharedMemorySize, (int)GRU_SMEM);

    const int M = N_NODES;
    const int gx = (M + 127) / 128;

    prep_kernel<<<(N_EDGES + 255) / 256, 256>>>(src, dst, et, W_in, We, W_ih, W_hh);
    zero_a<<<((N_NODES * HID / 4) + 255) / 256, 256>>>();

    // h = x @ W_in^T + b_in
    tf32_gemm_frag<IN_DIM, HID><<<dim3(gx, 1), 256, GEMM_SMEM>>>(x, pwin, b_in, ph, M);

    for (int s = 0; s < N_STEPS; s++) {
        tf32_gemm_frag<HID, NET * HID><<<dim3(gx, NET), 256, GEMM_SMEM>>>(ph, pwe, be, ptr, M);
        edge_scatter4<<<(N_EDGES / 4 * 16 + 255) / 256, 256>>>();
        gru_fused_tf32<<<(M + 63) / 64, 128, GRU_SMEM>>>(b_ih, b_hh, M);  // also zeroes g_a
    }

    zero_pool<<<1, 256>>>();
    pool_kernel<<<(M + 255) / 256, 64>>>(n2g);
    classifier_kernel<<<1, 128>>>(W1, b1, W2, b2, out);
}